// round 2
// baseline (speedup 1.0000x reference)
#include <cuda_runtime.h>
#include <cstdint>

// Scratch for S = softmax(0.5 * Q K^T) — 4096x4096 fp32 = 64 MB static device array.
__device__ float g_S[4096u * 4096u];

#define LDX 12288   // row stride of x in floats (3*64*64)
#define NQ  4096

__device__ __forceinline__ float tf32r(float x) {
    unsigned u;
    asm("cvt.rna.tf32.f32 %0, %1;" : "=r"(u) : "f"(x));
    return __uint_as_float(u);
}

__device__ __forceinline__ void mma_tf32(float* c, const unsigned* a, const unsigned* b) {
    asm volatile(
        "mma.sync.aligned.m16n8k8.row.col.f32.tf32.tf32.f32 "
        "{%0,%1,%2,%3}, {%4,%5,%6,%7}, {%8,%9}, {%0,%1,%2,%3};\n"
        : "+f"(c[0]), "+f"(c[1]), "+f"(c[2]), "+f"(c[3])
        : "r"(a[0]), "r"(a[1]), "r"(a[2]), "r"(a[3]), "r"(b[0]), "r"(b[1]));
}

// ---------------------------------------------------------------------------
// GEMM1 (3xTF32 split precision): S[i,j] = 0.5 * sum_k Q[i,k] * K[j,k]
// Q row i = x + i*LDX, K row j = x + j*LDX + 4096. Both K-contiguous (NT GEMM).
// Block tile 128x128, BK=16, 256 threads (8 warps, warp tile 64x32).
// a*b ~= hi(a)hi(b) + hi(a)lo(b) + lo(a)hi(b): logits accurate to ~1e-5.
// ---------------------------------------------------------------------------
__global__ __launch_bounds__(256)
void gemm_qk_kernel(const float* __restrict__ x) {
    __shared__ float Ah[128][20];
    __shared__ float Al[128][20];
    __shared__ float Bh[128][20];
    __shared__ float Bl[128][20];

    const int bm = blockIdx.y * 128;
    const int bn = blockIdx.x * 128;
    const int tid  = threadIdx.x;
    const int warp = tid >> 5;
    const int lane = tid & 31;
    const int wm = (warp >> 2) * 64;   // 2 warps along m
    const int wn = (warp & 3) * 32;    // 4 warps along n
    const int g  = lane >> 2;          // groupID
    const int tg = lane & 3;           // thread in group

    float acc[4][4][4];
    #pragma unroll
    for (int i = 0; i < 4; i++)
        #pragma unroll
        for (int j = 0; j < 4; j++)
            #pragma unroll
            for (int r = 0; r < 4; r++) acc[i][j][r] = 0.f;

    for (int k0 = 0; k0 < NQ; k0 += 16) {
        #pragma unroll
        for (int s = 0; s < 2; s++) {
            int f = tid + s * 256;
            int r = f >> 2;
            int c = (f & 3) << 2;
            float4 va = *(const float4*)(x + (size_t)(bm + r) * LDX + k0 + c);
            float4 vb = *(const float4*)(x + (size_t)(bn + r) * LDX + 4096 + k0 + c);
            float h;
            h = tf32r(va.x); Ah[r][c + 0] = h; Al[r][c + 0] = tf32r(va.x - h);
            h = tf32r(va.y); Ah[r][c + 1] = h; Al[r][c + 1] = tf32r(va.y - h);
            h = tf32r(va.z); Ah[r][c + 2] = h; Al[r][c + 2] = tf32r(va.z - h);
            h = tf32r(va.w); Ah[r][c + 3] = h; Al[r][c + 3] = tf32r(va.w - h);
            h = tf32r(vb.x); Bh[r][c + 0] = h; Bl[r][c + 0] = tf32r(vb.x - h);
            h = tf32r(vb.y); Bh[r][c + 1] = h; Bl[r][c + 1] = tf32r(vb.y - h);
            h = tf32r(vb.z); Bh[r][c + 2] = h; Bl[r][c + 2] = tf32r(vb.z - h);
            h = tf32r(vb.w); Bh[r][c + 3] = h; Bl[r][c + 3] = tf32r(vb.w - h);
        }
        __syncthreads();

        #pragma unroll
        for (int kk = 0; kk < 16; kk += 8) {
            unsigned ah[4][4], al[4][4], bh[4][2], bl[4][2];
            #pragma unroll
            for (int mi = 0; mi < 4; mi++) {
                int r = wm + mi * 16 + g;
                ah[mi][0] = __float_as_uint(Ah[r][kk + tg]);
                ah[mi][1] = __float_as_uint(Ah[r + 8][kk + tg]);
                ah[mi][2] = __float_as_uint(Ah[r][kk + tg + 4]);
                ah[mi][3] = __float_as_uint(Ah[r + 8][kk + tg + 4]);
                al[mi][0] = __float_as_uint(Al[r][kk + tg]);
                al[mi][1] = __float_as_uint(Al[r + 8][kk + tg]);
                al[mi][2] = __float_as_uint(Al[r][kk + tg + 4]);
                al[mi][3] = __float_as_uint(Al[r + 8][kk + tg + 4]);
            }
            #pragma unroll
            for (int ni = 0; ni < 4; ni++) {
                int cn = wn + ni * 8 + g;
                bh[ni][0] = __float_as_uint(Bh[cn][kk + tg]);
                bh[ni][1] = __float_as_uint(Bh[cn][kk + tg + 4]);
                bl[ni][0] = __float_as_uint(Bl[cn][kk + tg]);
                bl[ni][1] = __float_as_uint(Bl[cn][kk + tg + 4]);
            }
            #pragma unroll
            for (int mi = 0; mi < 4; mi++)
                #pragma unroll
                for (int ni = 0; ni < 4; ni++) {
                    mma_tf32(acc[mi][ni], al[mi], bh[ni]);
                    mma_tf32(acc[mi][ni], ah[mi], bl[ni]);
                    mma_tf32(acc[mi][ni], ah[mi], bh[ni]);
                }
        }
        __syncthreads();
    }

    #pragma unroll
    for (int mi = 0; mi < 4; mi++) {
        #pragma unroll
        for (int ni = 0; ni < 4; ni++) {
            int row = bm + wm + mi * 16 + g;
            int col = bn + wn + ni * 8 + tg * 2;
            g_S[(size_t)row * NQ + col]            = 0.5f * acc[mi][ni][0];
            g_S[(size_t)row * NQ + col + 1]        = 0.5f * acc[mi][ni][1];
            g_S[(size_t)(row + 8) * NQ + col]      = 0.5f * acc[mi][ni][2];
            g_S[(size_t)(row + 8) * NQ + col + 1]  = 0.5f * acc[mi][ni][3];
        }
    }
}

// ---------------------------------------------------------------------------
// Row softmax on g_S, in place. One block (256 threads) per row, 16 elems/thread.
// ---------------------------------------------------------------------------
__global__ __launch_bounds__(256)
void softmax_kernel() {
    const int row = blockIdx.x;
    float4* p = (float4*)(g_S + (size_t)row * NQ);   // 1024 float4 per row
    const int t    = threadIdx.x;
    const int warp = t >> 5;
    const int lane = t & 31;
    __shared__ float red[8];

    float4 v[4];
    float m = -3.4e38f;
    #pragma unroll
    for (int i = 0; i < 4; i++) {
        v[i] = p[t + i * 256];
        m = fmaxf(m, fmaxf(fmaxf(v[i].x, v[i].y), fmaxf(v[i].z, v[i].w)));
    }
    #pragma unroll
    for (int o = 16; o > 0; o >>= 1) m = fmaxf(m, __shfl_xor_sync(0xffffffffu, m, o));
    if (lane == 0) red[warp] = m;
    __syncthreads();
    m = red[0];
    #pragma unroll
    for (int i = 1; i < 8; i++) m = fmaxf(m, red[i]);
    __syncthreads();

    float sum = 0.f;
    #pragma unroll
    for (int i = 0; i < 4; i++) {
        v[i].x = __expf(v[i].x - m); v[i].y = __expf(v[i].y - m);
        v[i].z = __expf(v[i].z - m); v[i].w = __expf(v[i].w - m);
        sum += v[i].x + v[i].y + v[i].z + v[i].w;
    }
    #pragma unroll
    for (int o = 16; o > 0; o >>= 1) sum += __shfl_xor_sync(0xffffffffu, sum, o);
    if (lane == 0) red[warp] = sum;
    __syncthreads();
    sum = red[0];
    #pragma unroll
    for (int i = 1; i < 8; i++) sum += red[i];
    float inv = 1.f / sum;

    #pragma unroll
    for (int i = 0; i < 4; i++) {
        v[i].x *= inv; v[i].y *= inv; v[i].z *= inv; v[i].w *= inv;
        p[t + i * 256] = v[i];
    }
}

// ---------------------------------------------------------------------------
// GEMM2 (single tf32 — P in [0,1], error ~2e-4): O[i,j] = sum_k P[i,k] * V[k,j]
// P row i = g_S + i*4096 (K-contiguous). V row k = x + k*LDX + 8192 (N-contiguous).
// ---------------------------------------------------------------------------
__global__ __launch_bounds__(256, 2)
void gemm_pv_kernel(const float* __restrict__ x, float* __restrict__ out) {
    __shared__ float As[128][20];    // [m][k]
    __shared__ float Bs[16][132];    // [k][n], pad->stride 132

    const int bm = blockIdx.y * 128;
    const int bn = blockIdx.x * 128;
    const int tid  = threadIdx.x;
    const int warp = tid >> 5;
    const int lane = tid & 31;
    const int wm = (warp >> 2) * 64;
    const int wn = (warp & 3) * 32;
    const int g  = lane >> 2;
    const int tg = lane & 3;

    float acc[4][4][4];
    #pragma unroll
    for (int i = 0; i < 4; i++)
        #pragma unroll
        for (int j = 0; j < 4; j++)
            #pragma unroll
            for (int r = 0; r < 4; r++) acc[i][j][r] = 0.f;

    for (int k0 = 0; k0 < NQ; k0 += 16) {
        #pragma unroll
        for (int s = 0; s < 2; s++) {
            int f = tid + s * 256;
            // A tile: 128 rows x 16 k
            int ra = f >> 2;
            int ca = (f & 3) << 2;
            float4 va = *(const float4*)(g_S + (size_t)(bm + ra) * NQ + k0 + ca);
            As[ra][ca + 0] = tf32r(va.x); As[ra][ca + 1] = tf32r(va.y);
            As[ra][ca + 2] = tf32r(va.z); As[ra][ca + 3] = tf32r(va.w);
            // B tile: 16 k-rows x 128 n
            int rb = f >> 5;
            int cb = (f & 31) << 2;
            float4 vb = *(const float4*)(x + (size_t)(k0 + rb) * LDX + 8192 + bn + cb);
            Bs[rb][cb + 0] = tf32r(vb.x); Bs[rb][cb + 1] = tf32r(vb.y);
            Bs[rb][cb + 2] = tf32r(vb.z); Bs[rb][cb + 3] = tf32r(vb.w);
        }
        __syncthreads();

        #pragma unroll
        for (int kk = 0; kk < 16; kk += 8) {
            unsigned a[4][4], b[4][2];
            #pragma unroll
            for (int mi = 0; mi < 4; mi++) {
                int r = wm + mi * 16 + g;
                a[mi][0] = __float_as_uint(As[r][kk + tg]);
                a[mi][1] = __float_as_uint(As[r + 8][kk + tg]);
                a[mi][2] = __float_as_uint(As[r][kk + tg + 4]);
                a[mi][3] = __float_as_uint(As[r + 8][kk + tg + 4]);
            }
            #pragma unroll
            for (int ni = 0; ni < 4; ni++) {
                int cn = wn + ni * 8 + g;
                b[ni][0] = __float_as_uint(Bs[kk + tg][cn]);
                b[ni][1] = __float_as_uint(Bs[kk + tg + 4][cn]);
            }
            #pragma unroll
            for (int mi = 0; mi < 4; mi++)
                #pragma unroll
                for (int ni = 0; ni < 4; ni++)
                    mma_tf32(acc[mi][ni], a[mi], b[ni]);
        }
        __syncthreads();
    }

    #pragma unroll
    for (int mi = 0; mi < 4; mi++) {
        #pragma unroll
        for (int ni = 0; ni < 4; ni++) {
            int row = bm + wm + mi * 16 + g;
            int col = bn + wn + ni * 8 + tg * 2;
            out[(size_t)row * NQ + col]           = acc[mi][ni][0];
            out[(size_t)row * NQ + col + 1]       = acc[mi][ni][1];
            out[(size_t)(row + 8) * NQ + col]     = acc[mi][ni][2];
            out[(size_t)(row + 8) * NQ + col + 1] = acc[mi][ni][3];
        }
    }
}

extern "C" void kernel_launch(void* const* d_in, const int* in_sizes, int n_in,
                              void* d_out, int out_size) {
    const float* x = (const float*)d_in[0];
    float* out = (float*)d_out;
    (void)in_sizes; (void)n_in; (void)out_size;

    dim3 grid(32, 32), block(256);
    gemm_qk_kernel<<<grid, block>>>(x);
    softmax_kernel<<<4096, 256>>>();
    gemm_pv_kernel<<<grid, block>>>(x, out);
}

// round 8
// speedup vs baseline: 2.4527x; 2.4527x over previous
#include <cuda_runtime.h>
#include <cuda_bf16.h>
#include <cstdint>

// ---------------------------------------------------------------------------
// Static scratch (no allocs allowed).
// ---------------------------------------------------------------------------
__device__ float         g_S [4096u * 4096u];   // logits (fp32), 64 MB
__device__ __nv_bfloat16 g_Qh[4096u * 4096u], g_Ql[4096u * 4096u];
__device__ __nv_bfloat16 g_Kh[4096u * 4096u], g_Kl[4096u * 4096u];
__device__ __nv_bfloat16 g_Vh[4096u * 4096u], g_Vl[4096u * 4096u];  // V transposed: Vt[n][k]
__device__ __nv_bfloat16 g_Ph[4096u * 4096u], g_Pl[4096u * 4096u];

#define LDX 12288
#define NQ  4096

// ---------------------------------------------------------------------------
// PTX helpers — base-target only (sm_80-era): cp.async, ldmatrix, mma.sync.
// ---------------------------------------------------------------------------
__device__ __forceinline__ uint32_t smem_u32(const void* p) {
    uint32_t a;
    asm("{ .reg .u64 t; cvta.to.shared.u64 t, %1; cvt.u32.u64 %0, t; }" : "=r"(a) : "l"(p));
    return a;
}
__device__ __forceinline__ void cp_async16(uint32_t s, const void* g) {
    asm volatile("cp.async.cg.shared.global [%0], [%1], 16;" :: "r"(s), "l"(g));
}
#define CP_COMMIT() asm volatile("cp.async.commit_group;" ::: "memory")
#define CP_WAIT0()  asm volatile("cp.async.wait_group 0;" ::: "memory")

__device__ __forceinline__ void ldsm_x4(unsigned* r, uint32_t a) {
    asm volatile("ldmatrix.sync.aligned.m8n8.x4.shared.b16 {%0,%1,%2,%3}, [%4];"
                 : "=r"(r[0]), "=r"(r[1]), "=r"(r[2]), "=r"(r[3]) : "r"(a));
}
__device__ __forceinline__ void ldsm_x2(unsigned* r, uint32_t a) {
    asm volatile("ldmatrix.sync.aligned.m8n8.x2.shared.b16 {%0,%1}, [%2];"
                 : "=r"(r[0]), "=r"(r[1]) : "r"(a));
}
__device__ __forceinline__ void mma_bf16(float* c, const unsigned* a, const unsigned* b) {
    asm volatile(
        "mma.sync.aligned.m16n8k16.row.col.f32.bf16.bf16.f32 "
        "{%0,%1,%2,%3}, {%4,%5,%6,%7}, {%8,%9}, {%0,%1,%2,%3};\n"
        : "+f"(c[0]), "+f"(c[1]), "+f"(c[2]), "+f"(c[3])
        : "r"(a[0]), "r"(a[1]), "r"(a[2]), "r"(a[3]), "r"(b[0]), "r"(b[1]));
}

// ---------------------------------------------------------------------------
// Split helpers: fp32 -> bf16 hi + bf16 lo (lo = round(x - hi)).
// ---------------------------------------------------------------------------
__device__ __forceinline__ void split4_store(float4 v, __nv_bfloat16* hi, __nv_bfloat16* lo, size_t idx) {
    __nv_bfloat162 h01, h23, l01, l23;
    h01.x = __float2bfloat16(v.x); h01.y = __float2bfloat16(v.y);
    h23.x = __float2bfloat16(v.z); h23.y = __float2bfloat16(v.w);
    l01.x = __float2bfloat16(v.x - __bfloat162float(h01.x));
    l01.y = __float2bfloat16(v.y - __bfloat162float(h01.y));
    l23.x = __float2bfloat16(v.z - __bfloat162float(h23.x));
    l23.y = __float2bfloat16(v.w - __bfloat162float(h23.y));
    *(__nv_bfloat162*)(hi + idx)     = h01;
    *(__nv_bfloat162*)(hi + idx + 2) = h23;
    *(__nv_bfloat162*)(lo + idx)     = l01;
    *(__nv_bfloat162*)(lo + idx + 2) = l23;
}

__global__ __launch_bounds__(256)
void convert_qk_kernel(const float* __restrict__ x) {
    size_t gid = (size_t)blockIdx.x * 256 + threadIdx.x;   // 4M threads
    int i = (int)(gid >> 10);
    int c = (int)(gid & 1023) << 2;
    float4 q = *(const float4*)(x + (size_t)i * LDX + c);
    float4 k = *(const float4*)(x + (size_t)i * LDX + 4096 + c);
    size_t idx = (size_t)i * NQ + c;
    split4_store(q, g_Qh, g_Ql, idx);
    split4_store(k, g_Kh, g_Kl, idx);
}

// V transpose + split: Vt[n][k] = V[k][n], 32x32 tiles.
__global__ __launch_bounds__(256)
void convert_v_kernel(const float* __restrict__ x) {
    __shared__ float t[32][33];
    int n0 = blockIdx.x * 32, k0 = blockIdx.y * 32;
    int tx = threadIdx.x & 31, ty = threadIdx.x >> 5;
    #pragma unroll
    for (int j = 0; j < 4; j++) {
        int k = k0 + ty + j * 8;
        t[ty + j * 8][tx] = x[(size_t)k * LDX + 8192 + n0 + tx];
    }
    __syncthreads();
    #pragma unroll
    for (int j = 0; j < 4; j++) {
        int n = n0 + ty + j * 8;
        float v = t[tx][ty + j * 8];
        __nv_bfloat16 h = __float2bfloat16(v);
        __nv_bfloat16 l = __float2bfloat16(v - __bfloat162float(h));
        g_Vh[(size_t)n * NQ + k0 + tx] = h;
        g_Vl[(size_t)n * NQ + k0 + tx] = l;
    }
}

// ---------------------------------------------------------------------------
// bf16-split GEMM: out[M,N] = scale * (Ahi+Alo)(Bhi+Blo)^T  (3 products)
// A, B K-major [row][4096]. Tile 128x128, BK=64 (128B rows, XOR-8 swizzle),
// 2-stage cp.async double buffer, 256 threads, 8 warps (warp tile 64x32).
// ---------------------------------------------------------------------------
#define ARR_BYTES   16384            // 128 rows x 128 B
#define STAGE_BYTES (4 * ARR_BYTES)  // Ahi|Alo|Bhi|Blo = 64 KB
#define GSMEM_TOTAL (2 * STAGE_BYTES)

__global__ __launch_bounds__(256, 1)
void gemm_bf16_kernel(const __nv_bfloat16* __restrict__ Ah, const __nv_bfloat16* __restrict__ Al,
                      const __nv_bfloat16* __restrict__ Bh, const __nv_bfloat16* __restrict__ Bl,
                      float* __restrict__ out, float scale) {
    extern __shared__ __align__(128) char smem[];
    const uint32_t sb0 = smem_u32(smem);

    const int tid  = threadIdx.x;
    const int warp = tid >> 5;
    const int lane = tid & 31;
    const int bm = blockIdx.y * 128;
    const int bn = blockIdx.x * 128;
    const int wm = (warp >> 2) * 64;
    const int wn = (warp & 3) * 32;
    const int g  = lane >> 2;
    const int tg = lane & 3;

    const __nv_bfloat16* srcs[4] = {Ah, Al, Bh, Bl};

    // producer mapping: 4 x 16B per array per thread
    const int prow = tid >> 3;
    const int pch  = tid & 7;

    auto issue_stage = [&](int c) {
        const int k0 = c << 6;
        const uint32_t st = sb0 + (uint32_t)(c & 1) * STAGE_BYTES;
        #pragma unroll
        for (int arr = 0; arr < 4; arr++) {
            const __nv_bfloat16* src = srcs[arr];
            const int rb = (arr < 2) ? bm : bn;
            const uint32_t ab = st + arr * ARR_BYTES;
            #pragma unroll
            for (int j = 0; j < 4; j++) {
                const int row = prow + j * 32;
                const void* gp = src + (size_t)(rb + row) * NQ + k0 + pch * 8;
                cp_async16(ab + row * 128 + ((pch ^ (row & 7)) * 16), gp);
            }
        }
    };

    float acc[4][4][4];
    #pragma unroll
    for (int i = 0; i < 4; i++)
        #pragma unroll
        for (int j = 0; j < 4; j++)
            #pragma unroll
            for (int r = 0; r < 4; r++) acc[i][j][r] = 0.f;

    // fragment address bases
    const int arow = wm + (lane & 15);          // + mi*16
    const uint32_t aoff = (uint32_t)arow * 128;
    const int asw = arow & 7;
    const int csa = lane >> 4;                  // k-chunk select (0/1)
    const int lb  = lane & 15;
    const int brow = wn + (lb & 7);             // + ni*8
    const uint32_t boff = (uint32_t)brow * 128;
    const int bsw = brow & 7;
    const int csb = lb >> 3;

    issue_stage(0);
    CP_COMMIT();

    for (int c = 0; c < 64; ++c) {
        CP_WAIT0();
        __syncthreads();
        if (c + 1 < 64) { issue_stage(c + 1); CP_COMMIT(); }

        const uint32_t st = sb0 + (uint32_t)(c & 1) * STAGE_BYTES;
        #pragma unroll
        for (int kk = 0; kk < 4; kk++) {
            const uint32_t swzA = (uint32_t)(((kk * 2 + csa) ^ asw) * 16);
            const uint32_t swzB = (uint32_t)(((kk * 2 + csb) ^ bsw) * 16);
            unsigned ah[4][4], al[4][4], bh[4][2], bl[4][2];
            #pragma unroll
            for (int mi = 0; mi < 4; mi++) {
                const uint32_t aA = st + aoff + mi * 2048 + swzA;
                ldsm_x4(ah[mi], aA);
                ldsm_x4(al[mi], aA + ARR_BYTES);
            }
            #pragma unroll
            for (int ni = 0; ni < 4; ni++) {
                const uint32_t aB = st + 2 * ARR_BYTES + boff + ni * 1024 + swzB;
                ldsm_x2(bh[ni], aB);
                ldsm_x2(bl[ni], aB + ARR_BYTES);
            }
            #pragma unroll
            for (int mi = 0; mi < 4; mi++)
                #pragma unroll
                for (int ni = 0; ni < 4; ni++) {
                    mma_bf16(acc[mi][ni], ah[mi], bh[ni]);
                    mma_bf16(acc[mi][ni], ah[mi], bl[ni]);
                    mma_bf16(acc[mi][ni], al[mi], bh[ni]);
                }
        }
        __syncthreads();
    }

    // epilogue
    #pragma unroll
    for (int mi = 0; mi < 4; mi++) {
        #pragma unroll
        for (int ni = 0; ni < 4; ni++) {
            const int row = bm + wm + mi * 16 + g;
            const int col = bn + wn + ni * 8 + tg * 2;
            float2 v0 = { scale * acc[mi][ni][0], scale * acc[mi][ni][1] };
            float2 v1 = { scale * acc[mi][ni][2], scale * acc[mi][ni][3] };
            *(float2*)(out + (size_t)row * NQ + col)       = v0;
            *(float2*)(out + (size_t)(row + 8) * NQ + col) = v1;
        }
    }
}

// ---------------------------------------------------------------------------
// Row softmax: reads g_S fp32, writes P as bf16 hi/lo.
// ---------------------------------------------------------------------------
__global__ __launch_bounds__(256)
void softmax_kernel() {
    const int row = blockIdx.x;
    const float4* p = (const float4*)(g_S + (size_t)row * NQ);
    const int t = threadIdx.x, warp = t >> 5, lane = t & 31;
    __shared__ float red[8];

    float4 v[4];
    float m = -3.4e38f;
    #pragma unroll
    for (int i = 0; i < 4; i++) {
        v[i] = p[t + i * 256];
        m = fmaxf(m, fmaxf(fmaxf(v[i].x, v[i].y), fmaxf(v[i].z, v[i].w)));
    }
    #pragma unroll
    for (int o = 16; o > 0; o >>= 1) m = fmaxf(m, __shfl_xor_sync(0xffffffffu, m, o));
    if (lane == 0) red[warp] = m;
    __syncthreads();
    m = red[0];
    #pragma unroll
    for (int i = 1; i < 8; i++) m = fmaxf(m, red[i]);
    __syncthreads();

    float sum = 0.f;
    #pragma unroll
    for (int i = 0; i < 4; i++) {
        v[i].x = __expf(v[i].x - m); v[i].y = __expf(v[i].y - m);
        v[i].z = __expf(v[i].z - m); v[i].w = __expf(v[i].w - m);
        sum += v[i].x + v[i].y + v[i].z + v[i].w;
    }
    #pragma unroll
    for (int o = 16; o > 0; o >>= 1) sum += __shfl_xor_sync(0xffffffffu, sum, o);
    if (lane == 0) red[warp] = sum;
    __syncthreads();
    sum = red[0];
    #pragma unroll
    for (int i = 1; i < 8; i++) sum += red[i];
    const float inv = 1.f / sum;

    #pragma unroll
    for (int i = 0; i < 4; i++) {
        v[i].x *= inv; v[i].y *= inv; v[i].z *= inv; v[i].w *= inv;
        size_t idx = (size_t)row * NQ + (size_t)(t + i * 256) * 4;
        split4_store(v[i], g_Ph, g_Pl, idx);
    }
}

// ---------------------------------------------------------------------------
extern "C" void kernel_launch(void* const* d_in, const int* in_sizes, int n_in,
                              void* d_out, int out_size) {
    const float* x = (const float*)d_in[0];
    float* out = (float*)d_out;
    (void)in_sizes; (void)n_in; (void)out_size;

    cudaFuncSetAttribute(gemm_bf16_kernel, cudaFuncAttributeMaxDynamicSharedMemorySize, GSMEM_TOTAL);

    void *qh, *ql, *kh, *kl, *vh, *vl, *ph, *pl, *sS;
    cudaGetSymbolAddress(&qh, g_Qh); cudaGetSymbolAddress(&ql, g_Ql);
    cudaGetSymbolAddress(&kh, g_Kh); cudaGetSymbolAddress(&kl, g_Kl);
    cudaGetSymbolAddress(&vh, g_Vh); cudaGetSymbolAddress(&vl, g_Vl);
    cudaGetSymbolAddress(&ph, g_Ph); cudaGetSymbolAddress(&pl, g_Pl);
    cudaGetSymbolAddress(&sS, g_S);

    convert_qk_kernel<<<16384, 256>>>(x);
    convert_v_kernel<<<dim3(128, 128), 256>>>(x);

    dim3 grid(32, 32);
    gemm_bf16_kernel<<<grid, 256, GSMEM_TOTAL>>>(
        (const __nv_bfloat16*)qh, (const __nv_bfloat16*)ql,
        (const __nv_bfloat16*)kh, (const __nv_bfloat16*)kl,
        (float*)sS, 0.5f);

    softmax_kernel<<<4096, 256>>>();

    gemm_bf16_kernel<<<grid, 256, GSMEM_TOTAL>>>(
        (const __nv_bfloat16*)ph, (const __nv_bfloat16*)pl,
        (const __nv_bfloat16*)vh, (const __nv_bfloat16*)vl,
        out, 1.0f);
}